// round 2
// baseline (speedup 1.0000x reference)
#include <cuda_runtime.h>
#include <cuda_fp16.h>
#include <cstdint>
#include <cstddef>

// ---------------------------------------------------------------------------
// CSABlock: center/max reduce -> 3x conv1x1(+BN/ReLU) -> flash attention
//           (4096x4096 softmax per batch, fused) -> conv1x1 + residual.
// Shapes: N=4, C=256, D=9, H=W=64 (HW=4096), IC=128.  fp16 compute / fp32 acc,
// residual path exact fp32.
// ---------------------------------------------------------------------------

#define NB  4
#define CC  256
#define DD  9
#define HWV 4096
#define ICV 128

// Scratch (device globals: allocation-free per harness rules)
__device__ __align__(16) __half g_centerT[NB * HWV * CC];   // [n][hw][c]
__device__ __align__(16) __half g_xmaxT [NB * HWV * CC];    // [n][hw][c]
__device__ __align__(16) float  g_centerC[(size_t)NB * CC * HWV]; // [n][c][hw] fp32
__device__ __align__(16) __half g_theta [NB * HWV * ICV];   // [n][hw][ic]
__device__ __align__(16) __half g_phi   [NB * HWV * ICV];   // [n][hw][ic]
__device__ __align__(16) __half g_gmat  [NB * ICV * HWV];   // [n][ic][hw]
__device__ __align__(16) __half g_wT    [NB * HWV * ICV];   // weighted^T [n][hw][ic]

__device__ __forceinline__ uint32_t pkf(float a, float b) {
    __half2 h = __floats2half2_rn(a, b);
    return *reinterpret_cast<uint32_t*>(&h);
}
__device__ __forceinline__ uint32_t pkh(__half a, __half b) {
    __half2 h = __halves2half2(a, b);
    return *reinterpret_cast<uint32_t*>(&h);
}
__device__ __forceinline__ float ex2(float x) {
    float y;
    asm("ex2.approx.ftz.f32 %0, %1;" : "=f"(y) : "f"(x));
    return y;
}

// m16n8k16 row.col f16 -> f32 accumulate
__device__ __forceinline__ void mma16816(float* d, const uint32_t* a,
                                         uint32_t b0, uint32_t b1) {
    asm volatile(
        "mma.sync.aligned.m16n8k16.row.col.f32.f16.f16.f32 "
        "{%0,%1,%2,%3},{%4,%5,%6,%7},{%8,%9},{%0,%1,%2,%3};\n"
        : "+f"(d[0]), "+f"(d[1]), "+f"(d[2]), "+f"(d[3])
        : "r"(a[0]), "r"(a[1]), "r"(a[2]), "r"(a[3]), "r"(b0), "r"(b1));
}

// ---------------------------------------------------------------------------
// Stage A: depth-max + center slice (d = D/2+1 = 5). Writes fp32 residual
// [n][c][hw] and fp16 transposed [n][hw][c] tiles for the projection GEMMs.
// grid (64 hw-tiles, 4 c-tiles, 4 n), 256 threads. Tile: 64c x 64hw.
// ---------------------------------------------------------------------------
__global__ void __launch_bounds__(256) prep_kernel(const float* __restrict__ feature) {
    int hwt = blockIdx.x, ct = blockIdx.y, n = blockIdx.z;
    int t = threadIdx.x, w = t >> 5, lane = t & 31;
    int hwb = hwt * 64;
    __shared__ __half cs[64][66];
    __shared__ __half xs[64][66];

    for (int r = w; r < 64; r += 8) {
        int c = ct * 64 + r;
        const float* f = feature + ((size_t)(n * CC + c) * DD) * (size_t)HWV + hwb + lane * 2;
        float2 mx = *(const float2*)f;
        float2 ce = make_float2(0.f, 0.f);
#pragma unroll
        for (int d = 1; d < DD; d++) {
            float2 v = *(const float2*)(f + (size_t)d * HWV);
            if (d == 5) ce = v;
            mx.x = fmaxf(mx.x, v.x);
            mx.y = fmaxf(mx.y, v.y);
        }
        *(float2*)(g_centerC + (size_t)(n * CC + c) * HWV + hwb + lane * 2) = ce;
        cs[r][lane * 2]     = __float2half(ce.x);
        cs[r][lane * 2 + 1] = __float2half(ce.y);
        xs[r][lane * 2]     = __float2half(mx.x);
        xs[r][lane * 2 + 1] = __float2half(mx.y);
    }
    __syncthreads();

    int hl = t >> 2, cseg = (t & 3) * 16;
    size_t ob = (size_t)((size_t)n * HWV + hwb + hl) * CC + ct * 64 + cseg;
#pragma unroll
    for (int jj = 0; jj < 2; jj++) {
        int cb = cseg + jj * 8;
        uint4 vc, vx;
        vc.x = pkh(cs[cb + 0][hl], cs[cb + 1][hl]);
        vc.y = pkh(cs[cb + 2][hl], cs[cb + 3][hl]);
        vc.z = pkh(cs[cb + 4][hl], cs[cb + 5][hl]);
        vc.w = pkh(cs[cb + 6][hl], cs[cb + 7][hl]);
        vx.x = pkh(xs[cb + 0][hl], xs[cb + 1][hl]);
        vx.y = pkh(xs[cb + 2][hl], xs[cb + 3][hl]);
        vx.z = pkh(xs[cb + 4][hl], xs[cb + 5][hl]);
        vx.w = pkh(xs[cb + 6][hl], xs[cb + 7][hl]);
        *(uint4*)(g_centerT + ob + jj * 8) = vc;
        *(uint4*)(g_xmaxT  + ob + jj * 8) = vx;
    }
}

// ---------------------------------------------------------------------------
// Stage B: projections. out[hw][ic] = sum_c A[hw][c] * W[ic][c]  (K=256)
// z=0: theta (center, BN+ReLU); z=1: phi (xmax, BN+ReLU); z=2: g (xmax, raw,
// stored transposed [ic][hw]).
// grid (32 hw-tiles, 4 n, 3), 256 threads; warp = 16 q-rows x 128 ic.
// ---------------------------------------------------------------------------
__global__ void __launch_bounds__(256) proj_kernel(
    const float* __restrict__ wth, const float* __restrict__ wph, const float* __restrict__ wg,
    const float* __restrict__ tg, const float* __restrict__ tb,
    const float* __restrict__ tm, const float* __restrict__ tv,
    const float* __restrict__ pg, const float* __restrict__ pb,
    const float* __restrict__ pm, const float* __restrict__ pv) {
    int qt = blockIdx.x, n = blockIdx.y, z = blockIdx.z;
    int t = threadIdx.x, w = t >> 5, lane = t & 31, lq = lane >> 2, lp = lane & 3;

    __shared__ float sc[128], sb2[128], sm2[128];
    __shared__ __align__(16) __half tr[128][130];

    if (z < 2 && t < 128) {
        const float* G = z ? pg : tg;
        const float* B = z ? pb : tb;
        const float* M = z ? pm : tm;
        const float* V = z ? pv : tv;
        sc[t]  = G[t] * rsqrtf(V[t] + 1e-5f);
        sb2[t] = B[t];
        sm2[t] = M[t];
    }
    __syncthreads();

    const float* W = (z == 0) ? wth : (z == 1) ? wph : wg;
    const __half* Ain = ((z == 0) ? g_centerT : g_xmaxT) + (size_t)n * HWV * CC;
    int qw = qt * 128 + w * 16;

    float acc[16][4];
#pragma unroll
    for (int i = 0; i < 16; i++)
#pragma unroll
        for (int j = 0; j < 4; j++) acc[i][j] = 0.f;

#pragma unroll 4
    for (int kc = 0; kc < 16; kc++) {
        uint32_t a[4];
        const __half* p = Ain + (size_t)(qw + lq) * CC + kc * 16 + lp * 2;
        a[0] = *(const uint32_t*)p;
        a[1] = *(const uint32_t*)(p + 8 * CC);
        a[2] = *(const uint32_t*)(p + 8);
        a[3] = *(const uint32_t*)(p + 8 * CC + 8);
#pragma unroll
        for (int nt = 0; nt < 16; nt++) {
            const float* wp = W + (size_t)(nt * 8 + lq) * CC + kc * 16 + lp * 2;
            float2 f0 = *(const float2*)wp;
            float2 f1 = *(const float2*)(wp + 8);
            mma16816(acc[nt], a, pkf(f0.x, f0.y), pkf(f1.x, f1.y));
        }
    }

    if (z < 2) {
        __half* out = (z ? g_phi : g_theta) + (size_t)n * HWV * ICV;
#pragma unroll
        for (int nt = 0; nt < 16; nt++) {
            int ic0 = nt * 8 + lp * 2;
            float v0 = fmaxf((acc[nt][0] - sm2[ic0    ]) * sc[ic0    ] + sb2[ic0    ], 0.f);
            float v1 = fmaxf((acc[nt][1] - sm2[ic0 + 1]) * sc[ic0 + 1] + sb2[ic0 + 1], 0.f);
            float v2 = fmaxf((acc[nt][2] - sm2[ic0    ]) * sc[ic0    ] + sb2[ic0    ], 0.f);
            float v3 = fmaxf((acc[nt][3] - sm2[ic0 + 1]) * sc[ic0 + 1] + sb2[ic0 + 1], 0.f);
            *(uint32_t*)(out + (size_t)(qw + lq) * ICV + ic0)     = pkf(v0, v1);
            *(uint32_t*)(out + (size_t)(qw + lq + 8) * ICV + ic0) = pkf(v2, v3);
        }
    } else {
        // stage to smem, then coalesced transposed store [ic][hw]
#pragma unroll
        for (int nt = 0; nt < 16; nt++) {
            int ic0 = nt * 8 + lp * 2;
            int r = w * 16 + lq;
            tr[ic0    ][r    ] = __float2half(acc[nt][0]);
            tr[ic0 + 1][r    ] = __float2half(acc[nt][1]);
            tr[ic0    ][r + 8] = __float2half(acc[nt][2]);
            tr[ic0 + 1][r + 8] = __float2half(acc[nt][3]);
        }
        __syncthreads();
        int row = t >> 1, half = t & 1;
        const uint32_t* sp = (const uint32_t*)&tr[row][half * 64];
        uint32_t* dp = (uint32_t*)(g_gmat + (size_t)(n * ICV + row) * HWV + qt * 128 + half * 64);
#pragma unroll
        for (int j = 0; j < 32; j++) dp[j] = sp[j];
    }
}

// ---------------------------------------------------------------------------
// Stage C: flash attention per (n, 128-q tile). K-tiles of 64, online softmax.
// S = theta(128x128) @ phi^T, P -> A-fragment in registers, O += P @ g^T.
// grid (32, 4), 256 threads (8 warps x 16 q-rows). One wave (128 CTAs).
// ---------------------------------------------------------------------------
__global__ void __launch_bounds__(256, 1) attn_kernel() {
    __shared__ __align__(16) __half sPhi[64][136];  // [k][ic], conflict-free
    __shared__ __align__(16) __half sG[128][72];    // [ic][k], conflict-free
    int qt = blockIdx.x, n = blockIdx.y;
    int t = threadIdx.x, w = t >> 5, lane = t & 31, lq = lane >> 2, lp = lane & 3;
    int qw = qt * 128 + w * 16;
    const float LOG2E = 1.4426950408889634f;

    // theta A-fragments held in registers for the whole k loop
    const __half* th = g_theta + (size_t)n * HWV * ICV;
    uint32_t aq[8][4];
#pragma unroll
    for (int kc = 0; kc < 8; kc++) {
        const __half* p = th + (size_t)(qw + lq) * ICV + kc * 16 + lp * 2;
        aq[kc][0] = *(const uint32_t*)p;
        aq[kc][1] = *(const uint32_t*)(p + 8 * ICV);
        aq[kc][2] = *(const uint32_t*)(p + 8);
        aq[kc][3] = *(const uint32_t*)(p + 8 * ICV + 8);
    }

    float o[16][4];
#pragma unroll
    for (int i = 0; i < 16; i++)
#pragma unroll
        for (int j = 0; j < 4; j++) o[i][j] = 0.f;
    float m0 = -1e30f, m1 = -1e30f, l0 = 0.f, l1 = 0.f;

    const __half* ph = g_phi  + (size_t)n * HWV * ICV;
    const __half* gm = g_gmat + (size_t)n * ICV * HWV;

    int rowA = t >> 2, c4 = t & 3;   // sPhi fill
    int rowG = t >> 1, hG = t & 1;   // sG fill

    for (int kt = 0; kt < 64; kt++) {
        int k0 = kt * 64;
        {
            const uint4* src = (const uint4*)(ph + (size_t)(k0 + rowA) * ICV);
            uint4* dst = (uint4*)&sPhi[rowA][0];
#pragma unroll
            for (int j = 0; j < 4; j++) dst[c4 * 4 + j] = src[c4 * 4 + j];
            const uint4* s2 = (const uint4*)(gm + (size_t)rowG * HWV + k0);
            uint4* d2 = (uint4*)&sG[rowG][0];
#pragma unroll
            for (int j = 0; j < 4; j++) d2[hG * 4 + j] = s2[hG * 4 + j];
        }
        __syncthreads();

        // S = theta @ phi^T : 16 q-rows x 64 k per warp
        float s[8][4];
#pragma unroll
        for (int i = 0; i < 8; i++)
#pragma unroll
            for (int j = 0; j < 4; j++) s[i][j] = 0.f;
#pragma unroll
        for (int kc = 0; kc < 8; kc++)
#pragma unroll
            for (int nt = 0; nt < 8; nt++) {
                uint32_t b0 = *(const uint32_t*)&sPhi[nt * 8 + lq][kc * 16 + lp * 2];
                uint32_t b1 = *(const uint32_t*)&sPhi[nt * 8 + lq][kc * 16 + lp * 2 + 8];
                mma16816(s[nt], aq[kc], b0, b1);
            }

        // online softmax (row lq -> *0, row lq+8 -> *1); quad-lane reduce
        float mx0 = -1e30f, mx1 = -1e30f;
#pragma unroll
        for (int nt = 0; nt < 8; nt++) {
            mx0 = fmaxf(mx0, fmaxf(s[nt][0], s[nt][1]));
            mx1 = fmaxf(mx1, fmaxf(s[nt][2], s[nt][3]));
        }
        mx0 = fmaxf(mx0, __shfl_xor_sync(0xffffffffu, mx0, 1));
        mx0 = fmaxf(mx0, __shfl_xor_sync(0xffffffffu, mx0, 2));
        mx1 = fmaxf(mx1, __shfl_xor_sync(0xffffffffu, mx1, 1));
        mx1 = fmaxf(mx1, __shfl_xor_sync(0xffffffffu, mx1, 2));
        float mn0 = fmaxf(m0, mx0), mn1 = fmaxf(m1, mx1);
        float sc0 = ex2((m0 - mn0) * LOG2E), sc1 = ex2((m1 - mn1) * LOG2E);
        m0 = mn0; m1 = mn1;
        float b0f = mn0 * LOG2E, b1f = mn1 * LOG2E;

        float ps0 = 0.f, ps1 = 0.f;
        uint32_t pa[4][4];   // P as A-fragments (pure register conversion)
#pragma unroll
        for (int nt = 0; nt < 8; nt++) {
            float p0 = ex2(s[nt][0] * LOG2E - b0f);
            float p1 = ex2(s[nt][1] * LOG2E - b0f);
            float p2 = ex2(s[nt][2] * LOG2E - b1f);
            float p3 = ex2(s[nt][3] * LOG2E - b1f);
            ps0 += p0 + p1;
            ps1 += p2 + p3;
            int kk = nt >> 1, h = nt & 1;
            pa[kk][2 * h]     = pkf(p0, p1);
            pa[kk][2 * h + 1] = pkf(p2, p3);
        }
        l0 = l0 * sc0 + ps0;
        l1 = l1 * sc1 + ps1;
#pragma unroll
        for (int nt = 0; nt < 16; nt++) {
            o[nt][0] *= sc0; o[nt][1] *= sc0;
            o[nt][2] *= sc1; o[nt][3] *= sc1;
        }

        // O += P @ g^T : 16 q-rows x 128 ic per warp
#pragma unroll
        for (int kk = 0; kk < 4; kk++)
#pragma unroll
            for (int nt = 0; nt < 16; nt++) {
                uint32_t b0 = *(const uint32_t*)&sG[nt * 8 + lq][kk * 16 + lp * 2];
                uint32_t b1 = *(const uint32_t*)&sG[nt * 8 + lq][kk * 16 + lp * 2 + 8];
                mma16816(o[nt], pa[kk], b0, b1);
            }
        __syncthreads();
    }

    // normalize + store weighted^T [hw][ic]
    l0 += __shfl_xor_sync(0xffffffffu, l0, 1);
    l0 += __shfl_xor_sync(0xffffffffu, l0, 2);
    l1 += __shfl_xor_sync(0xffffffffu, l1, 1);
    l1 += __shfl_xor_sync(0xffffffffu, l1, 2);
    float inv0 = 1.0f / l0, inv1 = 1.0f / l1;
    __half* wt = g_wT + (size_t)n * HWV * ICV;
#pragma unroll
    for (int nt = 0; nt < 16; nt++) {
        int ic0 = nt * 8 + lp * 2;
        *(uint32_t*)(wt + (size_t)(qw + lq) * ICV + ic0)     = pkf(o[nt][0] * inv0, o[nt][1] * inv0);
        *(uint32_t*)(wt + (size_t)(qw + lq + 8) * ICV + ic0) = pkf(o[nt][2] * inv1, o[nt][3] * inv1);
    }
}

// ---------------------------------------------------------------------------
// Stage D: out[n][c][hw] = sum_ic wT[n][hw][ic] * w_w[c][ic] + centerC.
// grid (64 hw-tiles, 4 n), 256 threads. Tile: 64 hw x 256 c (4 chunks of 64c).
// Thread micro-tile: 2 hw x 8 c; smem rows padded to 65 words (conflict-free).
// ---------------------------------------------------------------------------
__global__ void __launch_bounds__(256) final_kernel(const float* __restrict__ w_w,
                                                    float* __restrict__ out) {
    __shared__ __half sA[64][130];
    __shared__ __half sW[64][130];
    int hwt = blockIdx.x, n = blockIdx.y;
    int t = threadIdx.x;
    int tr = t & 31, tc = t >> 5;

    {   // load wT tile [64 hw][128 ic]
        int r = t >> 2, q = t & 3;
        const uint32_t* src = (const uint32_t*)(g_wT +
            (size_t)((size_t)n * HWV + hwt * 64 + r) * ICV);
        uint32_t* dstw = (uint32_t*)&sA[r][0];
#pragma unroll
        for (int j = 0; j < 16; j++) dstw[q * 16 + j] = src[q * 16 + j];
    }

    for (int cch = 0; cch < 4; cch++) {
        {   // load w_w chunk [64 c][128 ic], fp32 -> fp16
            int cl = t >> 2, q = t & 3;
            const float2* srcw = (const float2*)(w_w + (size_t)(cch * 64 + cl) * ICV + q * 32);
            uint32_t* dw = (uint32_t*)&sW[cl][q * 32];
#pragma unroll
            for (int j = 0; j < 16; j++) {
                float2 f = srcw[j];
                dw[j] = pkf(f.x, f.y);
            }
        }
        __syncthreads();

        float acc0[8], acc1[8];
#pragma unroll
        for (int j = 0; j < 8; j++) { acc0[j] = 0.f; acc1[j] = 0.f; }

#pragma unroll 4
        for (int ic2 = 0; ic2 < 64; ic2++) {
            float2 A0 = __half22float2(*(const __half2*)&sA[tr][ic2 * 2]);
            float2 A1 = __half22float2(*(const __half2*)&sA[tr + 32][ic2 * 2]);
#pragma unroll
            for (int j = 0; j < 8; j++) {
                float2 W2 = __half22float2(*(const __half2*)&sW[tc * 8 + j][ic2 * 2]);
                acc0[j] += A0.x * W2.x + A0.y * W2.y;
                acc1[j] += A1.x * W2.x + A1.y * W2.y;
            }
        }

#pragma unroll
        for (int j = 0; j < 8; j++) {
            int c = cch * 64 + tc * 8 + j;
            size_t base = (size_t)((size_t)n * CC + c) * HWV + hwt * 64;
            out[base + tr]      = acc0[j] + g_centerC[base + tr];
            out[base + tr + 32] = acc1[j] + g_centerC[base + tr + 32];
        }
        __syncthreads();
    }
}

// ---------------------------------------------------------------------------
extern "C" void kernel_launch(void* const* d_in, const int* in_sizes, int n_in,
                              void* d_out, int out_size) {
    const float* feature = (const float*)d_in[0];
    const float* w_theta = (const float*)d_in[1];
    const float* tg = (const float*)d_in[2];
    const float* tb = (const float*)d_in[3];
    const float* tm = (const float*)d_in[4];
    const float* tv = (const float*)d_in[5];
    const float* w_phi = (const float*)d_in[6];
    const float* pg = (const float*)d_in[7];
    const float* pb = (const float*)d_in[8];
    const float* pm = (const float*)d_in[9];
    const float* pv = (const float*)d_in[10];
    const float* w_g = (const float*)d_in[11];
    const float* w_w = (const float*)d_in[12];
    float* out = (float*)d_out;

    prep_kernel<<<dim3(64, 4, 4), 256>>>(feature);
    proj_kernel<<<dim3(32, 4, 3), 256>>>(w_theta, w_phi, w_g,
                                         tg, tb, tm, tv, pg, pb, pm, pv);
    attn_kernel<<<dim3(32, 4), 256>>>();
    final_kernel<<<dim3(64, 4), 256>>>(w_w, out);
}

// round 4
// speedup vs baseline: 1.0305x; 1.0305x over previous
#include <cuda_runtime.h>
#include <cuda_fp16.h>
#include <cstdint>
#include <cstddef>

// ---------------------------------------------------------------------------
// CSABlock: center/max reduce -> 3x conv1x1(+BN/ReLU) -> flash attention
//           (4096x4096 softmax per batch, fused) -> conv1x1 + residual.
// Shapes: N=4, C=256, D=9, H=W=64 (HW=4096), IC=128.  fp16 compute / fp32 acc,
// residual path exact fp32.
// ---------------------------------------------------------------------------

#define NB  4
#define CC  256
#define DD  9
#define HWV 4096
#define ICV 128

// Scratch (device globals: allocation-free per harness rules)
__device__ __align__(16) __half g_centerT[NB * HWV * CC];   // [n][hw][c]
__device__ __align__(16) __half g_xmaxT [NB * HWV * CC];    // [n][hw][c]
__device__ __align__(16) float  g_centerC[(size_t)NB * CC * HWV]; // [n][c][hw] fp32
__device__ __align__(16) __half g_theta [NB * HWV * ICV];   // [n][hw][ic]
__device__ __align__(16) __half g_phi   [NB * HWV * ICV];   // [n][hw][ic]
__device__ __align__(16) __half g_gmat  [NB * ICV * HWV];   // [n][ic][hw]
__device__ __align__(16) __half g_wT    [NB * HWV * ICV];   // weighted^T [n][hw][ic]

__device__ __forceinline__ uint32_t pkf(float a, float b) {
    __half2 h = __floats2half2_rn(a, b);
    return *reinterpret_cast<uint32_t*>(&h);
}
__device__ __forceinline__ uint32_t pkh(__half a, __half b) {
    __half2 h = __halves2half2(a, b);
    return *reinterpret_cast<uint32_t*>(&h);
}
__device__ __forceinline__ float ex2(float x) {
    float y;
    asm("ex2.approx.ftz.f32 %0, %1;" : "=f"(y) : "f"(x));
    return y;
}

// m16n8k16 row.col f16 -> f32 accumulate
__device__ __forceinline__ void mma16816(float* d, const uint32_t* a,
                                         uint32_t b0, uint32_t b1) {
    asm volatile(
        "mma.sync.aligned.m16n8k16.row.col.f32.f16.f16.f32 "
        "{%0,%1,%2,%3},{%4,%5,%6,%7},{%8,%9},{%0,%1,%2,%3};\n"
        : "+f"(d[0]), "+f"(d[1]), "+f"(d[2]), "+f"(d[3])
        : "r"(a[0]), "r"(a[1]), "r"(a[2]), "r"(a[3]), "r"(b0), "r"(b1));
}

__device__ __forceinline__ void cpasync16(uint32_t saddr, const void* g) {
    asm volatile("cp.async.cg.shared.global [%0], [%1], 16;\n"
                 :: "r"(saddr), "l"(g));
}

// ---------------------------------------------------------------------------
// Stage A: depth-max + center slice (d = D/2+1 = 5). Writes fp32 residual
// [n][c][hw] and fp16 transposed [n][hw][c] tiles for the projection GEMMs.
// grid (64 hw-tiles, 4 c-tiles, 4 n), 256 threads. Tile: 64c x 64hw.
// ---------------------------------------------------------------------------
__global__ void __launch_bounds__(256) prep_kernel(const float* __restrict__ feature) {
    int hwt = blockIdx.x, ct = blockIdx.y, n = blockIdx.z;
    int t = threadIdx.x, w = t >> 5, lane = t & 31;
    int hwb = hwt * 64;
    __shared__ __half cs[64][66];
    __shared__ __half xs[64][66];

    for (int r = w; r < 64; r += 8) {
        int c = ct * 64 + r;
        const float* f = feature + ((size_t)(n * CC + c) * DD) * (size_t)HWV + hwb + lane * 2;
        float2 mx = *(const float2*)f;
        float2 ce = make_float2(0.f, 0.f);
#pragma unroll
        for (int d = 1; d < DD; d++) {
            float2 v = *(const float2*)(f + (size_t)d * HWV);
            if (d == 5) ce = v;
            mx.x = fmaxf(mx.x, v.x);
            mx.y = fmaxf(mx.y, v.y);
        }
        *(float2*)(g_centerC + (size_t)(n * CC + c) * HWV + hwb + lane * 2) = ce;
        cs[r][lane * 2]     = __float2half(ce.x);
        cs[r][lane * 2 + 1] = __float2half(ce.y);
        xs[r][lane * 2]     = __float2half(mx.x);
        xs[r][lane * 2 + 1] = __float2half(mx.y);
    }
    __syncthreads();

    int hl = t >> 2, cseg = (t & 3) * 16;
    size_t ob = (size_t)((size_t)n * HWV + hwb + hl) * CC + ct * 64 + cseg;
#pragma unroll
    for (int jj = 0; jj < 2; jj++) {
        int cb = cseg + jj * 8;
        uint4 vc, vx;
        vc.x = pkh(cs[cb + 0][hl], cs[cb + 1][hl]);
        vc.y = pkh(cs[cb + 2][hl], cs[cb + 3][hl]);
        vc.z = pkh(cs[cb + 4][hl], cs[cb + 5][hl]);
        vc.w = pkh(cs[cb + 6][hl], cs[cb + 7][hl]);
        vx.x = pkh(xs[cb + 0][hl], xs[cb + 1][hl]);
        vx.y = pkh(xs[cb + 2][hl], xs[cb + 3][hl]);
        vx.z = pkh(xs[cb + 4][hl], xs[cb + 5][hl]);
        vx.w = pkh(xs[cb + 6][hl], xs[cb + 7][hl]);
        *(uint4*)(g_centerT + ob + jj * 8) = vc;
        *(uint4*)(g_xmaxT  + ob + jj * 8) = vx;
    }
}

// ---------------------------------------------------------------------------
// Stage B: projections. out[hw][ic] = sum_c A[hw][c] * W[ic][c]  (K=256)
// z=0: theta (center, BN+ReLU); z=1: phi (xmax, BN+ReLU); z=2: g (xmax, raw,
// stored transposed [ic][hw]).
// grid (32 hw-tiles, 4 n, 3), 256 threads; warp = 16 q-rows x 128 ic.
// ---------------------------------------------------------------------------
__global__ void __launch_bounds__(256) proj_kernel(
    const float* __restrict__ wth, const float* __restrict__ wph, const float* __restrict__ wg,
    const float* __restrict__ tg, const float* __restrict__ tb,
    const float* __restrict__ tm, const float* __restrict__ tv,
    const float* __restrict__ pg, const float* __restrict__ pb,
    const float* __restrict__ pm, const float* __restrict__ pv) {
    int qt = blockIdx.x, n = blockIdx.y, z = blockIdx.z;
    int t = threadIdx.x, w = t >> 5, lane = t & 31, lq = lane >> 2, lp = lane & 3;

    __shared__ float sc[128], sb2[128], sm2[128];
    __shared__ __align__(16) __half tr[128][130];

    if (z < 2 && t < 128) {
        const float* G = z ? pg : tg;
        const float* B = z ? pb : tb;
        const float* M = z ? pm : tm;
        const float* V = z ? pv : tv;
        sc[t]  = G[t] * rsqrtf(V[t] + 1e-5f);
        sb2[t] = B[t];
        sm2[t] = M[t];
    }
    __syncthreads();

    const float* W = (z == 0) ? wth : (z == 1) ? wph : wg;
    const __half* Ain = ((z == 0) ? g_centerT : g_xmaxT) + (size_t)n * HWV * CC;
    int qw = qt * 128 + w * 16;

    float acc[16][4];
#pragma unroll
    for (int i = 0; i < 16; i++)
#pragma unroll
        for (int j = 0; j < 4; j++) acc[i][j] = 0.f;

#pragma unroll 4
    for (int kc = 0; kc < 16; kc++) {
        uint32_t a[4];
        const __half* p = Ain + (size_t)(qw + lq) * CC + kc * 16 + lp * 2;
        a[0] = *(const uint32_t*)p;
        a[1] = *(const uint32_t*)(p + 8 * CC);
        a[2] = *(const uint32_t*)(p + 8);
        a[3] = *(const uint32_t*)(p + 8 * CC + 8);
#pragma unroll
        for (int nt = 0; nt < 16; nt++) {
            const float* wp = W + (size_t)(nt * 8 + lq) * CC + kc * 16 + lp * 2;
            float2 f0 = *(const float2*)wp;
            float2 f1 = *(const float2*)(wp + 8);
            mma16816(acc[nt], a, pkf(f0.x, f0.y), pkf(f1.x, f1.y));
        }
    }

    if (z < 2) {
        __half* out = (z ? g_phi : g_theta) + (size_t)n * HWV * ICV;
#pragma unroll
        for (int nt = 0; nt < 16; nt++) {
            int ic0 = nt * 8 + lp * 2;
            float v0 = fmaxf((acc[nt][0] - sm2[ic0    ]) * sc[ic0    ] + sb2[ic0    ], 0.f);
            float v1 = fmaxf((acc[nt][1] - sm2[ic0 + 1]) * sc[ic0 + 1] + sb2[ic0 + 1], 0.f);
            float v2 = fmaxf((acc[nt][2] - sm2[ic0    ]) * sc[ic0    ] + sb2[ic0    ], 0.f);
            float v3 = fmaxf((acc[nt][3] - sm2[ic0 + 1]) * sc[ic0 + 1] + sb2[ic0 + 1], 0.f);
            *(uint32_t*)(out + (size_t)(qw + lq) * ICV + ic0)     = pkf(v0, v1);
            *(uint32_t*)(out + (size_t)(qw + lq + 8) * ICV + ic0) = pkf(v2, v3);
        }
    } else {
        // stage to smem, then coalesced transposed store [ic][hw]
#pragma unroll
        for (int nt = 0; nt < 16; nt++) {
            int ic0 = nt * 8 + lp * 2;
            int r = w * 16 + lq;
            tr[ic0    ][r    ] = __float2half(acc[nt][0]);
            tr[ic0 + 1][r    ] = __float2half(acc[nt][1]);
            tr[ic0    ][r + 8] = __float2half(acc[nt][2]);
            tr[ic0 + 1][r + 8] = __float2half(acc[nt][3]);
        }
        __syncthreads();
        int row = t >> 1, half = t & 1;
        const uint32_t* sp = (const uint32_t*)&tr[row][half * 64];
        uint32_t* dp = (uint32_t*)(g_gmat + (size_t)(n * ICV + row) * HWV + qt * 128 + half * 64);
#pragma unroll
        for (int j = 0; j < 32; j++) dp[j] = sp[j];
    }
}

// ---------------------------------------------------------------------------
// Stage C: flash attention per (n, 128-q tile). K-tiles of 64, online softmax.
// S = theta(128x128) @ phi^T, P -> A-fragment in registers, O += P @ g^T.
// cp.async double-buffered smem pipeline (2 x 35.8KB dynamic).
// grid (32, 4), 256 threads (8 warps x 16 q-rows). One wave (128 CTAs).
// ---------------------------------------------------------------------------
#define STG_H 17920           // halves per stage: 64*136 + 128*72
#define PHI_ROW 136
#define G_ROW 72
#define G_OFF 8704            // 64*136

extern __shared__ __half dynsmem[];

__global__ void __launch_bounds__(256, 1) attn_kernel() {
    int qt = blockIdx.x, n = blockIdx.y;
    int t = threadIdx.x, w = t >> 5, lane = t & 31, lq = lane >> 2, lp = lane & 3;
    int qw = qt * 128 + w * 16;
    const float LOG2E = 1.4426950408889634f;

    const __half* ph = g_phi  + (size_t)n * HWV * ICV;
    const __half* gm = g_gmat + (size_t)n * ICV * HWV;

    uint32_t sbase = (uint32_t)__cvta_generic_to_shared(dynsmem);
    int rowA = t >> 2, c4 = t & 3;   // sPhi fill: 64 rows x 128 halves
    int rowG = t >> 1, hG = t & 1;   // sG fill: 128 rows x 64 halves

    // theta A-fragments held in registers for the whole k loop
    const __half* th = g_theta + (size_t)n * HWV * ICV;
    uint32_t aq[8][4];
#pragma unroll
    for (int kc = 0; kc < 8; kc++) {
        const __half* p = th + (size_t)(qw + lq) * ICV + kc * 16 + lp * 2;
        aq[kc][0] = *(const uint32_t*)p;
        aq[kc][1] = *(const uint32_t*)(p + 8 * ICV);
        aq[kc][2] = *(const uint32_t*)(p + 8);
        aq[kc][3] = *(const uint32_t*)(p + 8 * ICV + 8);
    }

    float o[16][4];
#pragma unroll
    for (int i = 0; i < 16; i++)
#pragma unroll
        for (int j = 0; j < 4; j++) o[i][j] = 0.f;
    float m0 = -1e30f, m1 = -1e30f, l0 = 0.f, l1 = 0.f;

    // prefetch tile 0 into stage 0
    {
        uint32_t pdst = sbase + (uint32_t)(rowA * PHI_ROW) * 2;
        const __half* psrc = ph + (size_t)rowA * ICV;
        uint32_t gdst = sbase + (uint32_t)(G_OFF + rowG * G_ROW) * 2;
        const __half* gsrc = gm + (size_t)rowG * HWV;
#pragma unroll
        for (int j = 0; j < 4; j++) {
            int off = (c4 * 4 + j) * 8;
            cpasync16(pdst + off * 2, psrc + off);
        }
#pragma unroll
        for (int j = 0; j < 4; j++) {
            int off = (hG * 4 + j) * 8;
            cpasync16(gdst + off * 2, gsrc + off);
        }
        asm volatile("cp.async.commit_group;\n");
    }

    for (int kt = 0; kt < 64; kt++) {
        int st = kt & 1;
        if (kt + 1 < 64) {
            int k0n = (kt + 1) * 64;
            uint32_t so = (uint32_t)((st ^ 1) * STG_H) * 2;
            uint32_t pdst = sbase + so + (uint32_t)(rowA * PHI_ROW) * 2;
            const __half* psrc = ph + (size_t)(k0n + rowA) * ICV;
            uint32_t gdst = sbase + so + (uint32_t)(G_OFF + rowG * G_ROW) * 2;
            const __half* gsrc = gm + (size_t)rowG * HWV + k0n;
#pragma unroll
            for (int j = 0; j < 4; j++) {
                int off = (c4 * 4 + j) * 8;
                cpasync16(pdst + off * 2, psrc + off);
            }
#pragma unroll
            for (int j = 0; j < 4; j++) {
                int off = (hG * 4 + j) * 8;
                cpasync16(gdst + off * 2, gsrc + off);
            }
            asm volatile("cp.async.commit_group;\n");
            asm volatile("cp.async.wait_group 1;\n");
        } else {
            asm volatile("cp.async.wait_group 0;\n");
        }
        __syncthreads();

        const __half* P = dynsmem + st * STG_H;
        const __half* G = P + G_OFF;

        // S = theta @ phi^T : 16 q-rows x 64 k per warp
        float s[8][4];
#pragma unroll
        for (int i = 0; i < 8; i++)
#pragma unroll
            for (int j = 0; j < 4; j++) s[i][j] = 0.f;
#pragma unroll
        for (int kc = 0; kc < 8; kc++)
#pragma unroll
            for (int nt = 0; nt < 8; nt++) {
                uint32_t b0 = *(const uint32_t*)&P[(nt * 8 + lq) * PHI_ROW + kc * 16 + lp * 2];
                uint32_t b1 = *(const uint32_t*)&P[(nt * 8 + lq) * PHI_ROW + kc * 16 + lp * 2 + 8];
                mma16816(s[nt], aq[kc], b0, b1);
            }

        // online softmax (row lq -> *0, row lq+8 -> *1); quad-lane reduce
        float mx0 = -1e30f, mx1 = -1e30f;
#pragma unroll
        for (int nt = 0; nt < 8; nt++) {
            mx0 = fmaxf(mx0, fmaxf(s[nt][0], s[nt][1]));
            mx1 = fmaxf(mx1, fmaxf(s[nt][2], s[nt][3]));
        }
        mx0 = fmaxf(mx0, __shfl_xor_sync(0xffffffffu, mx0, 1));
        mx0 = fmaxf(mx0, __shfl_xor_sync(0xffffffffu, mx0, 2));
        mx1 = fmaxf(mx1, __shfl_xor_sync(0xffffffffu, mx1, 1));
        mx1 = fmaxf(mx1, __shfl_xor_sync(0xffffffffu, mx1, 2));
        float mn0 = fmaxf(m0, mx0), mn1 = fmaxf(m1, mx1);
        float sc0 = ex2((m0 - mn0) * LOG2E), sc1 = ex2((m1 - mn1) * LOG2E);
        m0 = mn0; m1 = mn1;
        float b0f = mn0 * LOG2E, b1f = mn1 * LOG2E;

        float ps0 = 0.f, ps1 = 0.f;
        uint32_t pa[4][4];   // P as A-fragments (pure register conversion)
#pragma unroll
        for (int nt = 0; nt < 8; nt++) {
            float p0 = ex2(s[nt][0] * LOG2E - b0f);
            float p1 = ex2(s[nt][1] * LOG2E - b0f);
            float p2 = ex2(s[nt][2] * LOG2E - b1f);
            float p3 = ex2(s[nt][3] * LOG2E - b1f);
            ps0 += p0 + p1;
            ps1 += p2 + p3;
            int kk = nt >> 1, h = nt & 1;
            pa[kk][2 * h]     = pkf(p0, p1);
            pa[kk][2 * h + 1] = pkf(p2, p3);
        }
        l0 = l0 * sc0 + ps0;
        l1 = l1 * sc1 + ps1;
#pragma unroll
        for (int nt = 0; nt < 16; nt++) {
            o[nt][0] *= sc0; o[nt][1] *= sc0;
            o[nt][2] *= sc1; o[nt][3] *= sc1;
        }

        // O += P @ g^T : 16 q-rows x 128 ic per warp
#pragma unroll
        for (int kk = 0; kk < 4; kk++)
#pragma unroll
            for (int nt = 0; nt < 16; nt++) {
                uint32_t b0 = *(const uint32_t*)&G[(nt * 8 + lq) * G_ROW + kk * 16 + lp * 2];
                uint32_t b1 = *(const uint32_t*)&G[(nt * 8 + lq) * G_ROW + kk * 16 + lp * 2 + 8];
                mma16816(o[nt], pa[kk], b0, b1);
            }
        __syncthreads();
    }

    // normalize + store weighted^T [hw][ic]
    l0 += __shfl_xor_sync(0xffffffffu, l0, 1);
    l0 += __shfl_xor_sync(0xffffffffu, l0, 2);
    l1 += __shfl_xor_sync(0xffffffffu, l1, 1);
    l1 += __shfl_xor_sync(0xffffffffu, l1, 2);
    float inv0 = 1.0f / l0, inv1 = 1.0f / l1;
    __half* wt = g_wT + (size_t)n * HWV * ICV;
#pragma unroll
    for (int nt = 0; nt < 16; nt++) {
        int ic0 = nt * 8 + lp * 2;
        *(uint32_t*)(wt + (size_t)(qw + lq) * ICV + ic0)     = pkf(o[nt][0] * inv0, o[nt][1] * inv0);
        *(uint32_t*)(wt + (size_t)(qw + lq + 8) * ICV + ic0) = pkf(o[nt][2] * inv1, o[nt][3] * inv1);
    }
}

// ---------------------------------------------------------------------------
// Stage D (tensor cores): out[n][c][hw] = sum_ic wT[n][hw][ic]*w_w[c][ic] + res.
// grid (32 hw-tiles, 4 n), 256 threads; CTA tile 128 hw x 256 c; K = 128.
// Warp = 16 hw x 256 c (acc[32][4]); epilogue via smem transpose, fused residual.
// ---------------------------------------------------------------------------
__global__ void __launch_bounds__(256) final_kernel(const float* __restrict__ w_w,
                                                    float* __restrict__ out) {
    __shared__ __align__(16) float sT[64][132];
    int hwt = blockIdx.x, n = blockIdx.y;
    int t = threadIdx.x, w = t >> 5, lane = t & 31, lq = lane >> 2, lp = lane & 3;
    int qw = hwt * 128 + w * 16;

    // A fragments: wT rows (16 hw x 128 ic per warp)
    const __half* wt = g_wT + (size_t)n * HWV * ICV;
    uint32_t aq[8][4];
#pragma unroll
    for (int kc = 0; kc < 8; kc++) {
        const __half* p = wt + (size_t)(qw + lq) * ICV + kc * 16 + lp * 2;
        aq[kc][0] = *(const uint32_t*)p;
        aq[kc][1] = *(const uint32_t*)(p + 8 * ICV);
        aq[kc][2] = *(const uint32_t*)(p + 8);
        aq[kc][3] = *(const uint32_t*)(p + 8 * ICV + 8);
    }

    float acc[32][4];
#pragma unroll
    for (int i = 0; i < 32; i++)
#pragma unroll
        for (int j = 0; j < 4; j++) acc[i][j] = 0.f;

#pragma unroll
    for (int kc = 0; kc < 8; kc++)
#pragma unroll
        for (int nt = 0; nt < 32; nt++) {
            const float* wp = w_w + (size_t)(nt * 8 + lq) * ICV + kc * 16 + lp * 2;
            float2 f0 = *(const float2*)wp;
            float2 f1 = *(const float2*)(wp + 8);
            mma16816(acc[nt], aq[kc], pkf(f0.x, f0.y), pkf(f1.x, f1.y));
        }

    // epilogue: 4 chunks of 64 c, smem transpose + residual, coalesced stores
    for (int cch = 0; cch < 4; cch++) {
        __syncthreads();
#pragma unroll
        for (int j = 0; j < 8; j++) {
            int nt = cch * 8 + j;
            int c = j * 8 + lp * 2;
            int r = w * 16 + lq;
            sT[c    ][r    ] = acc[nt][0];
            sT[c + 1][r    ] = acc[nt][1];
            sT[c    ][r + 8] = acc[nt][2];
            sT[c + 1][r + 8] = acc[nt][3];
        }
        __syncthreads();
        int cl = t >> 7, hw = t & 127;
#pragma unroll 8
        for (int it = 0; it < 32; it++) {
            int c_local = it * 2 + cl;
            int c = cch * 64 + c_local;
            size_t base = (size_t)((size_t)n * CC + c) * HWV + hwt * 128 + hw;
            out[base] = sT[c_local][hw] + g_centerC[base];
        }
    }
}

// ---------------------------------------------------------------------------
extern "C" void kernel_launch(void* const* d_in, const int* in_sizes, int n_in,
                              void* d_out, int out_size) {
    const float* feature = (const float*)d_in[0];
    const float* w_theta = (const float*)d_in[1];
    const float* tg = (const float*)d_in[2];
    const float* tb = (const float*)d_in[3];
    const float* tm = (const float*)d_in[4];
    const float* tv = (const float*)d_in[5];
    const float* w_phi = (const float*)d_in[6];
    const float* pg = (const float*)d_in[7];
    const float* pb = (const float*)d_in[8];
    const float* pm = (const float*)d_in[9];
    const float* pv = (const float*)d_in[10];
    const float* w_g = (const float*)d_in[11];
    const float* w_w = (const float*)d_in[12];
    float* out = (float*)d_out;

    cudaFuncSetAttribute(attn_kernel,
                         cudaFuncAttributeMaxDynamicSharedMemorySize,
                         2 * STG_H * (int)sizeof(__half));

    prep_kernel<<<dim3(64, 4, 4), 256>>>(feature);
    proj_kernel<<<dim3(32, 4, 3), 256>>>(w_theta, w_phi, w_g,
                                         tg, tb, tm, tv, pg, pb, pm, pv);
    attn_kernel<<<dim3(32, 4), 256, 2 * STG_H * (int)sizeof(__half)>>>();
    final_kernel<<<dim3(32, 4), 256>>>(w_w, out);
}